// round 1
// baseline (speedup 1.0000x reference)
#include <cuda_runtime.h>
#include <math.h>

// Shapes fixed by the problem definition.
#define Bv 4
#define Tv 2048
#define Dv 384
#define Hv 192
#define KC 32      // K-chunk for MLP smem tiling
#define RROWS 16   // rows per MLP block
#define PPB 16     // output positions per expansion block
#define NTHR 256

// Scratch (no allocs allowed): batch-0 durations, their cumsum, total.
__device__ float g_dur[Tv];
__device__ int   g_cum[Tv];
__device__ int   g_total;

__device__ __forceinline__ float duration_of(float z) {
    // softplus -> clamp to MIN_DUR=8 -> round (nearest-even, matching jnp.round)
    float sp = (z > 20.f) ? z : log1pf(expf(z));
    return rintf(fmaxf(sp, 8.f));
}

// One block (256 thr) computes durations for RROWS=16 rows starting at row0.
// Warp w owns rows (2w, 2w+1); lane owns 6 hidden columns {lane+32m}.
__device__ __forceinline__ void mlp_block(
    const float* __restrict__ x, const float* __restrict__ w1,
    const float* __restrict__ b1, const float* __restrict__ w2,
    const float* __restrict__ b2, int row0,
    float* s_w, float* s_x, float* __restrict__ dur_base)
{
    const int tid  = threadIdx.x;
    const int lane = tid & 31;
    const int warp = tid >> 5;
    const int r0 = warp * 2, r1 = r0 + 1;

    float a0[6], a1[6];
#pragma unroll
    for (int m = 0; m < 6; ++m) { a0[m] = 0.f; a1[m] = 0.f; }

    for (int kc = 0; kc < Dv; kc += KC) {
        // w1 tile [KC][Hv] (coalesced: inner index == global inner index)
        for (int i = tid; i < KC * Hv; i += NTHR)
            s_w[i] = w1[(long)(kc + i / Hv) * Hv + (i % Hv)];
        // x tile [RROWS][KC]
        for (int i = tid; i < RROWS * KC; i += NTHR)
            s_x[i] = x[(long)(row0 + i / KC) * Dv + kc + (i % KC)];
        __syncthreads();

#pragma unroll 4
        for (int kl = 0; kl < KC; ++kl) {
            float x0 = s_x[r0 * KC + kl];
            float x1 = s_x[r1 * KC + kl];
#pragma unroll
            for (int m = 0; m < 6; ++m) {
                float w = s_w[kl * Hv + lane + 32 * m];
                a0[m] = fmaf(x0, w, a0[m]);
                a1[m] = fmaf(x1, w, a1[m]);
            }
        }
        __syncthreads();
    }

    // epilogue: bias, relu, dot with w2, warp-reduce
    float p0 = 0.f, p1 = 0.f;
#pragma unroll
    for (int m = 0; m < 6; ++m) {
        int j = lane + 32 * m;
        float bb = b1[j], ww = w2[j];
        p0 += fmaxf(a0[m] + bb, 0.f) * ww;
        p1 += fmaxf(a1[m] + bb, 0.f) * ww;
    }
#pragma unroll
    for (int off = 16; off > 0; off >>= 1) {
        p0 += __shfl_xor_sync(0xffffffffu, p0, off);
        p1 += __shfl_xor_sync(0xffffffffu, p1, off);
    }
    if (lane == 0) {
        float bz = b2[0];
        dur_base[row0 + r0] = duration_of(p0 + bz);
        dur_base[row0 + r1] = duration_of(p1 + bz);
    }
}

// K1: durations for batch 0 (rows 0..Tv) -> g_dur
__global__ void mlp_kernel(const float* __restrict__ x, const float* __restrict__ w1,
                           const float* __restrict__ b1, const float* __restrict__ w2,
                           const float* __restrict__ b2)
{
    __shared__ float s_w[KC * Hv];
    __shared__ float s_x[RROWS * KC];
    mlp_block(x, w1, b1, w2, b2, blockIdx.x * RROWS, s_w, s_x, g_dur);
}

// K2: single-block inclusive scan of (int)g_dur -> g_cum, g_total.
// Also copies batch-0 durations into the duration_pred output tail.
__global__ void scan_kernel(float* __restrict__ out_tail)
{
    __shared__ int s_sum[256];
    const int tid = threadIdx.x;
    int loc[8]; int s = 0;
#pragma unroll
    for (int i = 0; i < 8; ++i) { loc[i] = (int)g_dur[tid * 8 + i]; s += loc[i]; }
    s_sum[tid] = s;
    __syncthreads();
#pragma unroll
    for (int off = 1; off < 256; off <<= 1) {
        int v = (tid >= off) ? s_sum[tid - off] : 0;
        __syncthreads();
        s_sum[tid] += v;
        __syncthreads();
    }
    int run = (tid > 0) ? s_sum[tid - 1] : 0;
#pragma unroll
    for (int i = 0; i < 8; ++i) { run += loc[i]; g_cum[tid * 8 + i] = run; }
    if (tid == 255) g_total = run;

    if (out_tail) {
        for (int i = tid; i < Tv; i += 256) out_tail[i] = g_dur[i];
    }
}

// K3: fused. First mlp_blocks blocks compute durations for batches 1..3
// (writing straight into the output tail); the rest do the expansion gather.
// MLP blocks lead the grid so their FMA work hides under the store traffic.
__global__ void fused_kernel(const float* __restrict__ x, const float* __restrict__ w1,
                             const float* __restrict__ b1, const float* __restrict__ w2,
                             const float* __restrict__ b2, float* __restrict__ out,
                             long TL, long tail_off, int mlp_blocks)
{
    __shared__ float s_w[KC * Hv];
    __shared__ float s_x[RROWS * KC];
    __shared__ int s_idx[PPB];
    __shared__ int s_ok[PPB];
    const int tid = threadIdx.x;

    if ((int)blockIdx.x < mlp_blocks) {
        int row0 = Tv + blockIdx.x * RROWS;   // rows Tv .. Bv*Tv-1
        mlp_block(x, w1, b1, w2, b2, row0, s_w, s_x, out + tail_off);
        return;
    }

    long p0 = (long)(blockIdx.x - mlp_blocks) * PPB;
    if (tid < PPB) {
        long p = p0 + tid;
        // searchsorted(cum, p, side="right") == upper_bound
        int lo = 0, hi = Tv;
        while (lo < hi) {
            int mid = (lo + hi) >> 1;
            if ((long)g_cum[mid] <= p) lo = mid + 1; else hi = mid;
        }
        s_idx[tid] = (lo < Tv) ? lo : (Tv - 1);
        s_ok[tid]  = (p < (long)g_total);
    }
    __syncthreads();

    const float4* __restrict__ x4 = (const float4*)x;
    float4* __restrict__ out4 = (float4*)out;
    const int VD = Dv / 4;                    // 96 float4 per row
    const float4 zf = make_float4(0.f, 0.f, 0.f, 0.f);

    for (int i = tid; i < PPB * Bv * VD; i += NTHR) {
        int v  = i % VD;
        int t2 = i / VD;
        int b  = t2 & 3;
        int pl = t2 >> 2;
        long p = p0 + pl;
        if (p >= TL) continue;
        float4 val = s_ok[pl] ? x4[((long)b * Tv + s_idx[pl]) * VD + v] : zf;
        out4[((long)b * TL + p) * VD + v] = val;
    }
}

extern "C" void kernel_launch(void* const* d_in, const int* in_sizes, int n_in,
                              void* d_out, int out_size)
{
    const float* x  = (const float*)d_in[0];
    const float* w1 = (const float*)d_in[1];
    const float* b1 = (const float*)d_in[2];
    const float* w2 = (const float*)d_in[3];
    const float* b2 = (const float*)d_in[4];
    float* out = (float*)d_out;

    // Output layout: expanded (Bv, TL, Dv) then duration_pred (Bv, Tv).
    // Discriminate tail presence by divisibility (Bv*Tv = 8192 is not a
    // multiple of Bv*Dv=1536 offset-wise: out_size % 1536 != 0 iff tail).
    long osz = (long)out_size;
    long TL, tail_off;
    int mlp_blocks;
    if (osz % ((long)Bv * Dv) == 0) {          // no duration tail in output
        TL = osz / ((long)Bv * Dv);
        tail_off = -1;
        mlp_blocks = 0;
    } else {
        TL = (osz - (long)Bv * Tv) / ((long)Bv * Dv);
        tail_off = (long)Bv * TL * Dv;
        mlp_blocks = (Bv - 1) * Tv / RROWS;     // 384 blocks for batches 1..3
    }
    int exp_blocks = (int)((TL + PPB - 1) / PPB);

    mlp_kernel<<<Tv / RROWS, NTHR>>>(x, w1, b1, w2, b2);
    scan_kernel<<<1, 256>>>(tail_off >= 0 ? out + tail_off : nullptr);
    fused_kernel<<<mlp_blocks + exp_blocks, NTHR>>>(x, w1, b1, w2, b2, out,
                                                    TL, tail_off, mlp_blocks);
}